// round 15
// baseline (speedup 1.0000x reference)
#include <cuda_runtime.h>
#include <cstdint>

// PANNAcceptor: out[b] = lin_w @ (W[x_{L-1}] ... W[x_0] e0) + lin_b
// Round 15: TMA-fed shared-memory fp24 steps.
//   Measured: every LDG-based variant (fp32 or fp24, any K) pins at
//   ~29 steps/us with ~512 warp-LDG/step -> the chip limiter is the LDG
//   REQUEST path (~15k warp-req/us), not bytes. TMA reaches the same LTS
//   byte cap with ~16 bulk requests/step instead of 512.
//   Per CTA: ring of 4 x 48KB smem buffers; cp.async.bulk prefetches
//   W24[x_{t+1}] chunk q right after chunk q of step t is consumed
//   (~1.2us slack). Compute reads smem (LDS, off the L2 request path),
//   decodes the validated fp24 lattice (rel_err 1.712e-4, gate 1e-3).
//   Target: 12.9GB / 7.5TB/s byte cap ~= 1.75ms.

#define NST  256
#define TPB  512          // 16 warps
#define MAXA 128
#define MAXB 1024
#define KCTA 64
#define ROWB   768        // packed row: 512B hi(u16) + 256B lo(u8)
#define SYMB   (NST * ROWB)          // 196608 B per symbol
#define CHUNKB (SYMB / 4)            // 49152 B per chunk (64 rows)
#define NCHUNK 4
#define BULKB  12288                 // 4 bulk copies per chunk

// dynamic smem layout
#define SM_H0    0                   // hbuf[0]: 1024 B
#define SM_H1    1024                // hbuf[1]: 1024 B
#define SM_MBAR  2048                // 4 mbarriers (32 B)
#define SM_W     4096                // 4 x 49152 B ring
#define SMEM_TOTAL (SM_W + NCHUNK * CHUNKB)   // 200704 B

__device__ unsigned char g_w24[(size_t)MAXA * SYMB];
__device__ int g_order[MAXB];
__device__ int g_next;

// ---------------- quantize: fp32 -> packed planar fp24 (R11 layout) --------
// decoded bits = (H<<16) | (L<<8) | L = H*65536 + L*257 (nearest lattice pt)
__global__ void pann_quant(const float* __restrict__ W, int total4)
{
    for (int i = blockIdx.x * blockDim.x + threadIdx.x; i < total4;
         i += gridDim.x * blockDim.x) {
        const float4 f = ((const float4*)W)[i];
        uint32_t u0 = __float_as_uint(f.x), u1 = __float_as_uint(f.y);
        uint32_t u2 = __float_as_uint(f.z), u3 = __float_as_uint(f.w);
        uint32_t l0 = ((u0 & 0xFFFFu) * 255u + 32768u) >> 16;
        uint32_t l1 = ((u1 & 0xFFFFu) * 255u + 32768u) >> 16;
        uint32_t l2 = ((u2 & 0xFFFFu) * 255u + 32768u) >> 16;
        uint32_t l3 = ((u3 & 0xFFFFu) * 255u + 32768u) >> 16;
        ushort4 h;
        h.x = (unsigned short)(u0 >> 16);
        h.y = (unsigned short)(u1 >> 16);
        h.z = (unsigned short)(u2 >> 16);
        h.w = (unsigned short)(u3 >> 16);

        const int col4 = i & 63;
        const int row  = i >> 6;
        unsigned char* rb = g_w24 + (size_t)row * ROWB;
        *(ushort4*)(rb + col4 * 8) = h;
        *(uint32_t*)(rb + 512 + col4 * 4) =
            l0 | (l1 << 8) | (l2 << 16) | (l3 << 24);
    }
}

// ---------------- scheduler: rank batches by (L desc, idx) ----------------
__global__ void pann_sched(const int* __restrict__ lengths, int B)
{
    const int tid = threadIdx.x;
    if (tid == 0) g_next = 0;
    if (tid < B) {
        const int L = lengths[tid];
        int rank = 0;
        for (int s = 0; s < B; ++s) {
            const int L2 = lengths[s];
            rank += (L2 > L) || (L2 == L && s < tid);
        }
        g_order[rank] = tid;
    }
}

// ---------------- helpers ----------------
__device__ __forceinline__ uint32_t smem_u32(const void* p) {
    uint32_t a;
    asm("{ .reg .u64 t; cvta.to.shared.u64 t, %1; cvt.u32.u64 %0, t; }" : "=r"(a) : "l"(p));
    return a;
}
__device__ __forceinline__ void mbar_init(uint32_t a, uint32_t n) {
    asm volatile("mbarrier.init.shared.b64 [%0], %1;" :: "r"(a), "r"(n) : "memory");
}
__device__ __forceinline__ void mbar_expect_tx(uint32_t a, uint32_t bytes) {
    asm volatile("mbarrier.arrive.expect_tx.shared.b64 _, [%0], %1;"
                 :: "r"(a), "r"(bytes) : "memory");
}
__device__ __forceinline__ void mbar_wait(uint32_t a, int parity) {
    asm volatile(
        "{\n\t"
        ".reg .pred P;\n\t"
        "W_%=:\n\t"
        "mbarrier.try_wait.parity.acquire.cta.shared::cta.b64 P, [%0], %1, 0x989680;\n\t"
        "@!P bra W_%=;\n\t"
        "}"
        :: "r"(a), "r"(parity) : "memory");
}
__device__ __forceinline__ void bulk_ld(uint32_t dst, const void* src, uint32_t sz,
                                        uint32_t mbar) {
    asm volatile(
        "cp.async.bulk.shared::cluster.global.mbarrier::complete_tx::bytes "
        "[%0], [%1], %2, [%3];"
        :: "r"(dst), "l"(src), "r"(sz), "r"(mbar) : "memory");
}
__device__ __forceinline__ float pf(uint32_t hw, uint32_t lw, uint32_t sel) {
    return __uint_as_float(__byte_perm(hw, lw, sel));
}
__device__ __forceinline__ float warp_reduce16(float v) {
    v += __shfl_xor_sync(0xffffffffu, v, 8);
    v += __shfl_xor_sync(0xffffffffu, v, 4);
    v += __shfl_xor_sync(0xffffffffu, v, 2);
    v += __shfl_xor_sync(0xffffffffu, v, 1);
    return v;
}

// ---------------- persistent TMA-fed LPT worker ----------------
__global__ __launch_bounds__(TPB, 1)
void pann_tma24(const int* __restrict__ xs,
                const int* __restrict__ lengths,
                const float* __restrict__ lin_w,
                const float* __restrict__ lin_b,
                float* __restrict__ out,
                int S, int B)
{
    extern __shared__ unsigned char smem[];
    float* hbuf0 = (float*)(smem + SM_H0);
    float* hbuf1 = (float*)(smem + SM_H1);
    __shared__ int s_b;

    const int tid  = threadIdx.x;
    const int warp = tid >> 5;
    const int lane = tid & 31;
    const uint32_t mb0 = smem_u32(smem + SM_MBAR);
    const uint32_t wsm = smem_u32(smem + SM_W);

    if (tid == 0) {
        #pragma unroll
        for (int q = 0; q < NCHUNK; ++q) mbar_init(mb0 + q * 8, 1);
    }
    __syncthreads();

    int par[NCHUNK] = {0, 0, 0, 0};

    for (;;) {
        if (tid == 0) {
            const int idx = atomicAdd(&g_next, 1);
            s_b = (idx < B) ? g_order[idx] : -1;
        }
        __syncthreads();
        const int b = s_b;
        if (b < 0) return;

        if (tid < NST) { hbuf0[tid] = (tid == 0) ? 1.0f : 0.0f; }

        const int L = lengths[b];
        const int* xrow = xs + (size_t)b * S;
        __syncthreads();

        // prolog: load all 4 chunks of W24[x0]
        int a = __ldg(xrow);
        if (tid == 0) {
            const unsigned char* sym = g_w24 + (size_t)a * SYMB;
            #pragma unroll
            for (int q = 0; q < NCHUNK; ++q) {
                mbar_expect_tx(mb0 + q * 8, CHUNKB);
                #pragma unroll
                for (int k = 0; k < CHUNKB / BULKB; ++k)
                    bulk_ld(wsm + q * CHUNKB + k * BULKB,
                            sym + q * CHUNKB + k * BULKB, BULKB, mb0 + q * 8);
            }
        }

        float* hsrc = hbuf0;
        float* hdst = hbuf1;

        for (int t = 0; t < L; ++t) {
            const bool more = (t + 1 < L);
            const int anext = more ? __ldg(xrow + t + 1) : 0;
            const unsigned char* symn = g_w24 + (size_t)anext * SYMB;

            // lane's h slice: cols [8l, 8l+8)
            const float4 h0 = ((const float4*)hsrc)[2 * lane];
            const float4 h1 = ((const float4*)hsrc)[2 * lane + 1];

            #pragma unroll
            for (int q = 0; q < NCHUNK; ++q) {
                mbar_wait(mb0 + q * 8, par[q]);
                par[q] ^= 1;

                // compute 64 rows of this chunk: warp w -> rows w*4 .. w*4+4
                const unsigned char* cb =
                    smem + SM_W + q * CHUNKB + (warp * 4) * ROWB + lane * 16;
                #pragma unroll
                for (int r = 0; r < 4; ++r) {
                    const uint4 H  = *(const uint4*)(cb + r * ROWB);
                    const uint2 Lw = *(const uint2*)(cb + r * ROWB + 512 - lane * 8);

                    const float e0 = pf(H.x, Lw.x, 0x1044u);
                    const float e1 = pf(H.x, Lw.x, 0x3255u);
                    const float e2 = pf(H.y, Lw.x, 0x1066u);
                    const float e3 = pf(H.y, Lw.x, 0x3277u);
                    const float e4 = pf(H.z, Lw.y, 0x1044u);
                    const float e5 = pf(H.z, Lw.y, 0x3255u);
                    const float e6 = pf(H.w, Lw.y, 0x1066u);
                    const float e7 = pf(H.w, Lw.y, 0x3277u);

                    float s = e0*h0.x + e1*h0.y + e2*h0.z + e3*h0.w
                            + e4*h1.x + e5*h1.y + e6*h1.z + e7*h1.w;

                    s += __shfl_xor_sync(0xffffffffu, s, 16);
                    s = warp_reduce16(s);
                    if (lane == 0) hdst[q * 64 + warp * 4 + r] = s;
                }
                __syncthreads();   // all reads of buffer q done

                // reissue buffer q with chunk q of W24[x_{t+1}]
                if (more && tid == 0) {
                    mbar_expect_tx(mb0 + q * 8, CHUNKB);
                    #pragma unroll
                    for (int k = 0; k < CHUNKB / BULKB; ++k)
                        bulk_ld(wsm + q * CHUNKB + k * BULKB,
                                symn + q * CHUNKB + k * BULKB, BULKB, mb0 + q * 8);
                }
            }
            // hdst complete (last __syncthreads); swap
            float* tmp = hsrc; hsrc = hdst; hdst = tmp;
        }

        // ---- linear head ----
        if (warp < 2) {
            float s = 0.0f;
            #pragma unroll
            for (int i = lane; i < NST; i += 32)
                s += lin_w[warp * NST + i] * hsrc[i];
            s += __shfl_xor_sync(0xffffffffu, s, 16);
            s = warp_reduce16(s);
            if (lane == 0) out[b * 2 + warp] = s + lin_b[warp];
        }
        __syncthreads();   // head reads hsrc before next batch reuses smem
    }
}

// ---------------- fallback (plain R1) for unexpected shapes ----------------
__global__ __launch_bounds__(512, 1)
void pann_chain_fp32(const int* __restrict__ xs,
                     const int* __restrict__ lengths,
                     const float* __restrict__ W,
                     const float* __restrict__ lin_w,
                     const float* __restrict__ lin_b,
                     float* __restrict__ out,
                     int S)
{
    __shared__ float hbuf[2][NST];
    const int b = blockIdx.x, tid = threadIdx.x, warp = tid >> 5, lane = tid & 31;
    if (tid < NST) hbuf[0][tid] = (tid == 0) ? 1.0f : 0.0f;
    const int L = lengths[b];
    const int* xrow = xs + (size_t)b * S;
    __syncthreads();
    int cur = 0;
    const int i0 = warp * 16;
    for (int t = 0; t < L; ++t) {
        const int a = __ldg(xrow + t);
        const float* Wa = W + (size_t)a * (NST * NST);
        const float* hsrc = hbuf[cur];
        float* hdst = hbuf[cur ^ 1];
        const float4 hA = ((const float4*)hsrc)[lane];
        const float4 hB = ((const float4*)hsrc)[32 + lane];
        #pragma unroll 4
        for (int r = 0; r < 16; ++r) {
            const int i = i0 + r;
            const float4* p = (const float4*)(Wa + (size_t)i * NST + lane * 4);
            const float4 wA = p[0];
            const float4 wB = p[32];
            float s = wA.x*hA.x + wA.y*hA.y + wA.z*hA.z + wA.w*hA.w
                    + wB.x*hB.x + wB.y*hB.y + wB.z*hB.z + wB.w*hB.w;
            s += __shfl_xor_sync(0xffffffffu, s, 16);
            s = warp_reduce16(s);
            if (lane == 0) hdst[i] = s;
        }
        __syncthreads();
        cur ^= 1;
    }
    const float* hf = hbuf[cur];
    if (warp < 2) {
        float s = 0.0f;
        #pragma unroll
        for (int i = lane; i < NST; i += 32) s += lin_w[warp * NST + i] * hf[i];
        s += __shfl_xor_sync(0xffffffffu, s, 16);
        s = warp_reduce16(s);
        if (lane == 0) out[b * 2 + warp] = s + lin_b[warp];
    }
}

extern "C" void kernel_launch(void* const* d_in, const int* in_sizes, int n_in,
                              void* d_out, int out_size)
{
    const int*   xs      = (const int*)d_in[0];
    const int*   lengths = (const int*)d_in[1];
    const float* W       = (const float*)d_in[2];
    const float* lin_w   = (const float*)d_in[3];
    const float* lin_b   = (const float*)d_in[4];
    float*       out     = (float*)d_out;

    const int B = in_sizes[1];
    const int S = in_sizes[0] / B;
    const int A = in_sizes[2] / (NST * NST);

    if (A >= 1 && A <= MAXA && B >= 1 && B <= MAXB) {
        static bool attr_set = false;
        if (!attr_set) {
            cudaFuncSetAttribute(pann_tma24,
                                 cudaFuncAttributeMaxDynamicSharedMemorySize,
                                 SMEM_TOTAL);
            attr_set = true;
        }
        const int total4 = in_sizes[2] / 4;
        pann_quant<<<2048, 256>>>(W, total4);
        const int sthreads = ((B + 31) / 32 * 32) < 32 ? 32 : ((B + 31) / 32 * 32);
        pann_sched<<<1, sthreads>>>(lengths, B);
        const int K = (B < KCTA) ? B : KCTA;
        pann_tma24<<<K, TPB, SMEM_TOTAL>>>(xs, lengths, lin_w, lin_b, out, S, B);
    } else {
        pann_chain_fp32<<<B, 512>>>(xs, lengths, W, lin_w, lin_b, out, S);
    }
}

// round 16
// speedup vs baseline: 1.1383x; 1.1383x over previous
#include <cuda_runtime.h>
#include <cstdint>

// PANNAcceptor: out[b] = lin_w @ (W[x_{L-1}] ... W[x_0] e0) + lin_b
// Round 16: warp-specialized TMA producer/consumer fp24 pipeline.
//   Established: every LDG variant pins at ~29.5 steps/us (=> >=2.21ms);
//   R11 (2210us) sits on that bound. R15's TMA feed self-limited at 0.37
//   steps/us/CTA because waits+syncs+serial reissue sat on the compute
//   critical path. This round moves ALL of that to a dedicated producer
//   warp (warp 16 of 17): it paces on per-chunk empty barriers and issues
//   cp.async.bulk; consumers only do {fast full-wait, smem compute, warp
//   arrive}, one named barrier per step. fp24 lattice decode unchanged
//   (rel_err 1.712e-4, gate 1e-3).

#define NST   256
#define TPB   544          // 16 consumer warps + 1 producer warp
#define NCW   16           // consumer warps
#define MAXA  128
#define MAXB  1024
#define KCTA  64
#define ROWB  768          // packed row: 512B hi(u16) + 256B lo(u8)
#define SYMB   (NST * ROWB)        // 196608 B per symbol
#define NCHUNK 4
#define CHUNKB (SYMB / NCHUNK)     // 49152 B (64 rows)
#define BULKB  12288               // 4 bulk copies per chunk

// dynamic smem layout
#define SM_H0    0
#define SM_H1    1024
#define SM_FULL  2048              // 4 mbarriers
#define SM_EMPTY 2112              // 4 mbarriers
#define SM_W     4096
#define SMEM_TOTAL (SM_W + SYMB)   // 200704 B

__device__ __align__(128) unsigned char g_w24[(size_t)MAXA * SYMB];
__device__ int g_order[MAXB];
__device__ int g_next;

// ---------------- quantize: fp32 -> packed planar fp24 (validated) ---------
// decoded bits = (H<<16) | (L<<8) | L = H*65536 + L*257 (nearest lattice pt)
__global__ void pann_quant(const float* __restrict__ W, int total4)
{
    for (int i = blockIdx.x * blockDim.x + threadIdx.x; i < total4;
         i += gridDim.x * blockDim.x) {
        const float4 f = ((const float4*)W)[i];
        uint32_t u0 = __float_as_uint(f.x), u1 = __float_as_uint(f.y);
        uint32_t u2 = __float_as_uint(f.z), u3 = __float_as_uint(f.w);
        uint32_t l0 = ((u0 & 0xFFFFu) * 255u + 32768u) >> 16;
        uint32_t l1 = ((u1 & 0xFFFFu) * 255u + 32768u) >> 16;
        uint32_t l2 = ((u2 & 0xFFFFu) * 255u + 32768u) >> 16;
        uint32_t l3 = ((u3 & 0xFFFFu) * 255u + 32768u) >> 16;
        ushort4 h;
        h.x = (unsigned short)(u0 >> 16);
        h.y = (unsigned short)(u1 >> 16);
        h.z = (unsigned short)(u2 >> 16);
        h.w = (unsigned short)(u3 >> 16);

        const int col4 = i & 63;
        const int row  = i >> 6;
        unsigned char* rb = g_w24 + (size_t)row * ROWB;
        *(ushort4*)(rb + col4 * 8) = h;                        // hi plane
        *(uint32_t*)(rb + 512 + col4 * 4) =
            l0 | (l1 << 8) | (l2 << 16) | (l3 << 24);          // lo plane
    }
}

// ---------------- scheduler: rank batches by (L desc, idx) ----------------
__global__ void pann_sched(const int* __restrict__ lengths, int B)
{
    const int tid = threadIdx.x;
    if (tid == 0) g_next = 0;
    if (tid < B) {
        const int L = lengths[tid];
        int rank = 0;
        for (int s = 0; s < B; ++s) {
            const int L2 = lengths[s];
            rank += (L2 > L) || (L2 == L && s < tid);
        }
        g_order[rank] = tid;
    }
}

// ---------------- helpers ----------------
__device__ __forceinline__ uint32_t smem_u32(const void* p) {
    uint32_t a;
    asm("{ .reg .u64 t; cvta.to.shared.u64 t, %1; cvt.u32.u64 %0, t; }" : "=r"(a) : "l"(p));
    return a;
}
__device__ __forceinline__ void mbar_init(uint32_t a, uint32_t n) {
    asm volatile("mbarrier.init.shared.b64 [%0], %1;" :: "r"(a), "r"(n) : "memory");
}
__device__ __forceinline__ void mbar_expect_tx(uint32_t a, uint32_t bytes) {
    asm volatile("mbarrier.arrive.expect_tx.shared.b64 _, [%0], %1;"
                 :: "r"(a), "r"(bytes) : "memory");
}
__device__ __forceinline__ void mbar_arrive(uint32_t a) {
    asm volatile("mbarrier.arrive.shared.b64 _, [%0];" :: "r"(a) : "memory");
}
__device__ __forceinline__ void mbar_wait(uint32_t a, int parity) {
    asm volatile(
        "{\n\t"
        ".reg .pred P;\n\t"
        "W_%=:\n\t"
        "mbarrier.try_wait.parity.acquire.cta.shared::cta.b64 P, [%0], %1, 0x989680;\n\t"
        "@!P bra W_%=;\n\t"
        "}"
        :: "r"(a), "r"(parity) : "memory");
}
__device__ __forceinline__ void bulk_ld(uint32_t dst, const void* src, uint32_t sz,
                                        uint32_t mbar) {
    asm volatile(
        "cp.async.bulk.shared::cluster.global.mbarrier::complete_tx::bytes "
        "[%0], [%1], %2, [%3];"
        :: "r"(dst), "l"(src), "r"(sz), "r"(mbar) : "memory");
}
__device__ __forceinline__ float pf(uint32_t hw, uint32_t lw, uint32_t sel) {
    return __uint_as_float(__byte_perm(hw, lw, sel));
}
__device__ __forceinline__ float warp_reduce16(float v) {
    v += __shfl_xor_sync(0xffffffffu, v, 8);
    v += __shfl_xor_sync(0xffffffffu, v, 4);
    v += __shfl_xor_sync(0xffffffffu, v, 2);
    v += __shfl_xor_sync(0xffffffffu, v, 1);
    return v;
}
#define BAR_ALL()  asm volatile("bar.sync 0, 544;" ::: "memory")
#define BAR_CONS() asm volatile("bar.sync 1, 512;" ::: "memory")

// ---------------- persistent warp-specialized LPT worker ----------------
__global__ __launch_bounds__(TPB, 1)
void pann_ws24(const int* __restrict__ xs,
               const int* __restrict__ lengths,
               const float* __restrict__ lin_w,
               const float* __restrict__ lin_b,
               float* __restrict__ out,
               int S, int B)
{
    extern __shared__ unsigned char smem[];
    float* hb0 = (float*)(smem + SM_H0);
    float* hb1 = (float*)(smem + SM_H1);
    __shared__ int s_b;

    const int tid  = threadIdx.x;
    const int warp = tid >> 5;
    const int lane = tid & 31;
    const uint32_t fullb  = smem_u32(smem + SM_FULL);
    const uint32_t emptyb = smem_u32(smem + SM_EMPTY);
    const uint32_t wsm    = smem_u32(smem + SM_W);

    if (tid == 0) {
        #pragma unroll
        for (int q = 0; q < NCHUNK; ++q) {
            mbar_init(fullb  + q * 8, 1);      // 1 expect_tx arrival per phase
            mbar_init(emptyb + q * 8, NCW);    // 16 consumer-warp arrivals
        }
    }
    BAR_ALL();

    int pfq[NCHUNK] = {0, 0, 0, 0};   // consumer parity on full[]
    int peq[NCHUNK] = {1, 1, 1, 1};   // producer parity on empty[] (first wait passes)

    for (;;) {
        if (tid == 0) {
            const int idx = atomicAdd(&g_next, 1);
            s_b = (idx < B) ? g_order[idx] : -1;
        }
        BAR_ALL();
        const int b = s_b;
        if (b < 0) return;

        const int L = lengths[b];
        const int* xrow = xs + (size_t)b * S;

        if (warp == NCW) {
            // =============== PRODUCER (lane 0 of warp 16) ===============
            if (lane == 0) {
                for (int t = 0; t < L; ++t) {
                    const int a = __ldg(xrow + t);
                    const unsigned char* sym = g_w24 + (size_t)a * SYMB;
                    #pragma unroll
                    for (int q = 0; q < NCHUNK; ++q) {
                        mbar_wait(emptyb + q * 8, peq[q]);   // buffer consumed
                        peq[q] ^= 1;
                        mbar_expect_tx(fullb + q * 8, CHUNKB);
                        #pragma unroll
                        for (int k = 0; k < CHUNKB / BULKB; ++k)
                            bulk_ld(wsm + q * CHUNKB + k * BULKB,
                                    sym + q * CHUNKB + k * BULKB,
                                    BULKB, fullb + q * 8);
                    }
                }
            }
            __syncwarp();
        } else {
            // =============== CONSUMERS (warps 0..15) ===============
            if (tid < NST) hb0[tid] = (tid == 0) ? 1.0f : 0.0f;
            BAR_CONS();

            float* hsrc = hb0;
            float* hdst = hb1;

            for (int t = 0; t < L; ++t) {
                // lane's h slice: cols [8l, 8l+8)
                const float4 h0 = ((const float4*)hsrc)[2 * lane];
                const float4 h1 = ((const float4*)hsrc)[2 * lane + 1];

                #pragma unroll
                for (int q = 0; q < NCHUNK; ++q) {
                    mbar_wait(fullb + q * 8, pfq[q]);
                    pfq[q] ^= 1;

                    // chunk q rows: q*64 .. q*64+63; this warp: 4 rows
                    const unsigned char* cb =
                        smem + SM_W + q * CHUNKB + (warp * 4) * ROWB + lane * 16;
                    #pragma unroll
                    for (int r = 0; r < 4; ++r) {
                        const uint4 H  = *(const uint4*)(cb + r * ROWB);
                        const uint2 Lw = *(const uint2*)(cb + r * ROWB + 512 - lane * 8);

                        const float e0 = pf(H.x, Lw.x, 0x1044u);
                        const float e1 = pf(H.x, Lw.x, 0x3255u);
                        const float e2 = pf(H.y, Lw.x, 0x1066u);
                        const float e3 = pf(H.y, Lw.x, 0x3277u);
                        const float e4 = pf(H.z, Lw.y, 0x1044u);
                        const float e5 = pf(H.z, Lw.y, 0x3255u);
                        const float e6 = pf(H.w, Lw.y, 0x1066u);
                        const float e7 = pf(H.w, Lw.y, 0x3277u);

                        float s = e0*h0.x + e1*h0.y + e2*h0.z + e3*h0.w
                                + e4*h1.x + e5*h1.y + e6*h1.z + e7*h1.w;

                        s += __shfl_xor_sync(0xffffffffu, s, 16);
                        s = warp_reduce16(s);
                        if (lane == 0) hdst[q * 64 + warp * 4 + r] = s;
                    }
                    __syncwarp();                       // all lanes done reading
                    if (lane == 0) mbar_arrive(emptyb + q * 8);
                }
                BAR_CONS();                             // hdst complete
                float* tmp = hsrc; hsrc = hdst; hdst = tmp;
            }

            // ---- linear head ----
            if (warp < 2) {
                float s = 0.0f;
                #pragma unroll
                for (int i = lane; i < NST; i += 32)
                    s += lin_w[warp * NST + i] * hsrc[i];
                s += __shfl_xor_sync(0xffffffffu, s, 16);
                s = warp_reduce16(s);
                if (lane == 0) out[b * 2 + warp] = s + lin_b[warp];
            }
            // loop-top BAR_ALL orders head reads before next batch's hb0 init
        }
    }
}

// ---------------- fallback (plain R1) for unexpected shapes ----------------
__global__ __launch_bounds__(512, 1)
void pann_chain_fp32(const int* __restrict__ xs,
                     const int* __restrict__ lengths,
                     const float* __restrict__ W,
                     const float* __restrict__ lin_w,
                     const float* __restrict__ lin_b,
                     float* __restrict__ out,
                     int S)
{
    __shared__ float hbuf[2][NST];
    const int b = blockIdx.x, tid = threadIdx.x, warp = tid >> 5, lane = tid & 31;
    if (tid < NST) hbuf[0][tid] = (tid == 0) ? 1.0f : 0.0f;
    const int L = lengths[b];
    const int* xrow = xs + (size_t)b * S;
    __syncthreads();
    int cur = 0;
    const int i0 = warp * 16;
    for (int t = 0; t < L; ++t) {
        const int a = __ldg(xrow + t);
        const float* Wa = W + (size_t)a * (NST * NST);
        const float* hsrc = hbuf[cur];
        float* hdst = hbuf[cur ^ 1];
        const float4 hA = ((const float4*)hsrc)[lane];
        const float4 hB = ((const float4*)hsrc)[32 + lane];
        #pragma unroll 4
        for (int r = 0; r < 16; ++r) {
            const int i = i0 + r;
            const float4* p = (const float4*)(Wa + (size_t)i * NST + lane * 4);
            const float4 wA = p[0];
            const float4 wB = p[32];
            float s = wA.x*hA.x + wA.y*hA.y + wA.z*hA.z + wA.w*hA.w
                    + wB.x*hB.x + wB.y*hB.y + wB.z*hB.z + wB.w*hB.w;
            s += __shfl_xor_sync(0xffffffffu, s, 16);
            s = warp_reduce16(s);
            if (lane == 0) hdst[i] = s;
        }
        __syncthreads();
        cur ^= 1;
    }
    const float* hf = hbuf[cur];
    if (warp < 2) {
        float s = 0.0f;
        #pragma unroll
        for (int i = lane; i < NST; i += 32) s += lin_w[warp * NST + i] * hf[i];
        s += __shfl_xor_sync(0xffffffffu, s, 16);
        s = warp_reduce16(s);
        if (lane == 0) out[b * 2 + warp] = s + lin_b[warp];
    }
}

extern "C" void kernel_launch(void* const* d_in, const int* in_sizes, int n_in,
                              void* d_out, int out_size)
{
    const int*   xs      = (const int*)d_in[0];
    const int*   lengths = (const int*)d_in[1];
    const float* W       = (const float*)d_in[2];
    const float* lin_w   = (const float*)d_in[3];
    const float* lin_b   = (const float*)d_in[4];
    float*       out     = (float*)d_out;

    const int B = in_sizes[1];
    const int S = in_sizes[0] / B;
    const int A = in_sizes[2] / (NST * NST);

    if (A >= 1 && A <= MAXA && B >= 1 && B <= MAXB) {
        static bool attr_set = false;
        if (!attr_set) {
            cudaFuncSetAttribute(pann_ws24,
                                 cudaFuncAttributeMaxDynamicSharedMemorySize,
                                 SMEM_TOTAL);
            attr_set = true;
        }
        const int total4 = in_sizes[2] / 4;
        pann_quant<<<2048, 256>>>(W, total4);
        const int sthreads = ((B + 31) / 32 * 32) < 32 ? 32 : ((B + 31) / 32 * 32);
        pann_sched<<<1, sthreads>>>(lengths, B);
        const int K = (B < KCTA) ? B : KCTA;
        pann_ws24<<<K, TPB, SMEM_TOTAL>>>(xs, lengths, lin_w, lin_b, out, S, B);
    } else {
        pann_chain_fp32<<<B, 512>>>(xs, lengths, W, lin_w, lin_b, out, S);
    }
}

// round 17
// speedup vs baseline: 1.2455x; 1.0942x over previous
#include <cuda_runtime.h>
#include <cstdint>

// PANNAcceptor: out[b] = lin_w @ (W[x_{L-1}] ... W[x_0] e0) + lin_b
// Round 17: TMA warp-specialized fp24 + forward/backward mid-split + LPT.
//   Established: LDG paths cap at ~29.5 steps/us (request path) -> >=2.21ms;
//   R11 sits on it. TMA escapes the request cap; at K=96 the chip becomes
//   LTS BYTE-capped: 12.6GB fp24 / ~7.3TB/s ~= 1.73ms. Mid-split halves the
//   max chain depth (1016->~508) so the tail hides under the bulk; LPT pops
//   forward halves strictly before their backward partners (deadlock-free).
//   fp24 lattice (decoded (H<<16)|(L<<8)|L) validated at rel 1.71e-4.

#define NST   256
#define TPB   544          // 16 consumer warps + 1 producer warp
#define NCW   16
#define MAXA  128
#define MAXB  128
#define KCTA  96
#define ROWB  768          // packed row: 512B hi(u16) + 256B lo(u8)
#define SYMB   (NST * ROWB)        // 196608
#define NCHUNK 4
#define CHUNKB (SYMB / NCHUNK)     // 49152 (64 rows)
#define SPLIT_MIN 32

// dynamic smem layout
#define SM_V     0                 // vbuf[2][2][256] f32 = 4096 B
#define SM_FULL  4096              // 4 mbarriers
#define SM_EMPTY 4160              // 4 mbarriers
#define SM_ITEM  4224              // int4
#define SM_W     4352              // 16B aligned
#define SMEM_TOTAL (SM_W + SYMB)   // 200960

__device__ __align__(128) unsigned char g_wf[(size_t)MAXA * SYMB];  // W packed
__device__ __align__(128) unsigned char g_wb[(size_t)MAXA * SYMB];  // W^T packed
__device__ float g_hmid[MAXB][NST];
__device__ int   g_flag[MAXB];
__device__ int4  g_items[2 * MAXB];     // {b, start, count, dir} 0=fwd,1=bwd,2=whole,3=skip
__device__ int   g_next;

// ---------------- quantize + transpose-pack ----------------
// lattice: decoded bits = (H<<16)|(L<<8)|L = H*65536 + L*257
__global__ void pann_qt(const float* __restrict__ W)
{
    __shared__ __align__(16) unsigned short sf_hi[32][32];
    __shared__ __align__(16) unsigned char  sf_lo[32][32];
    __shared__ __align__(16) unsigned short sb_hi[32][32];
    __shared__ __align__(16) unsigned char  sb_lo[32][32];

    const int a  = blockIdx.z;
    const int jt = blockIdx.y * 32;      // row tile
    const int ct = blockIdx.x * 32;      // col tile
    const int tx = threadIdx.x, ty = threadIdx.y;
    const int tid = ty * 32 + tx;
    const float* Wa = W + (size_t)a * NST * NST;

    #pragma unroll
    for (int k = 0; k < 4; ++k) {
        const int r = ty + 8 * k;
        const float v = Wa[(size_t)(jt + r) * NST + ct + tx];
        const uint32_t u = __float_as_uint(v);
        const uint32_t l = ((u & 0xFFFFu) * 255u + 32768u) >> 16;
        const unsigned short h = (unsigned short)(u >> 16);
        sf_hi[r][tx] = h;  sf_lo[r][tx] = (unsigned char)l;
        sb_hi[tx][r] = h;  sb_lo[tx][r] = (unsigned char)l;
    }
    __syncthreads();

    const uint32_t* fh = (const uint32_t*)sf_hi;
    const uint32_t* fl = (const uint32_t*)sf_lo;
    const uint32_t* bh = (const uint32_t*)sb_hi;
    const uint32_t* bl = (const uint32_t*)sb_lo;

    // f: rows jt+r, cols ct..ct+31 ; b: rows ct+r, cols jt..jt+31
    #pragma unroll
    for (int i = tid; i < 512; i += 256) {
        const int r = i >> 4, w = i & 15;
        *(uint32_t*)(g_wf + (size_t)(a * NST + jt + r) * ROWB + ct * 2 + w * 4) = fh[r * 16 + w];
        *(uint32_t*)(g_wb + (size_t)(a * NST + ct + r) * ROWB + jt * 2 + w * 4) = bh[r * 16 + w];
    }
    {
        const int r = tid >> 3, w = tid & 7;
        *(uint32_t*)(g_wf + (size_t)(a * NST + jt + r) * ROWB + 512 + ct + w * 4) = fl[r * 8 + w];
        *(uint32_t*)(g_wb + (size_t)(a * NST + ct + r) * ROWB + 512 + jt + w * 4) = bl[r * 8 + w];
    }
}

// ---------------- scheduler: chains desc by L; items = [fwd, bwd] pairs -----
__global__ void pann_sched(const int* __restrict__ lengths, int B)
{
    const int tid = threadIdx.x;
    if (tid == 0) g_next = 0;
    if (tid < B) {
        const int L = lengths[tid];
        int rank = 0;
        for (int s = 0; s < B; ++s) {
            const int L2 = lengths[s];
            rank += (L2 > L) || (L2 == L && s < tid);
        }
        if (L >= SPLIT_MIN) {
            const int M = L >> 1;
            g_items[2 * rank]     = make_int4(tid, 0, M, 0);       // fwd first!
            g_items[2 * rank + 1] = make_int4(tid, M, L - M, 1);   // bwd
        } else {
            g_items[2 * rank]     = make_int4(tid, 0, L, 2);
            g_items[2 * rank + 1] = make_int4(0, 0, 0, 3);
        }
        g_flag[tid] = 0;
    }
}

// ---------------- helpers ----------------
__device__ __forceinline__ uint32_t smem_u32(const void* p) {
    uint32_t a;
    asm("{ .reg .u64 t; cvta.to.shared.u64 t, %1; cvt.u32.u64 %0, t; }" : "=r"(a) : "l"(p));
    return a;
}
__device__ __forceinline__ void mbar_init(uint32_t a, uint32_t n) {
    asm volatile("mbarrier.init.shared.b64 [%0], %1;" :: "r"(a), "r"(n) : "memory");
}
__device__ __forceinline__ void mbar_expect_tx(uint32_t a, uint32_t bytes) {
    asm volatile("mbarrier.arrive.expect_tx.shared.b64 _, [%0], %1;"
                 :: "r"(a), "r"(bytes) : "memory");
}
__device__ __forceinline__ void mbar_arrive(uint32_t a) {
    asm volatile("mbarrier.arrive.shared.b64 _, [%0];" :: "r"(a) : "memory");
}
__device__ __forceinline__ void mbar_wait(uint32_t a, int parity) {
    asm volatile(
        "{\n\t.reg .pred P;\n\tW_%=:\n\t"
        "mbarrier.try_wait.parity.acquire.cta.shared::cta.b64 P, [%0], %1, 0x989680;\n\t"
        "@!P bra W_%=;\n\t}"
        :: "r"(a), "r"(parity) : "memory");
}
__device__ __forceinline__ void bulk_ld(uint32_t dst, const void* src, uint32_t sz,
                                        uint32_t mbar) {
    asm volatile(
        "cp.async.bulk.shared::cluster.global.mbarrier::complete_tx::bytes "
        "[%0], [%1], %2, [%3];"
        :: "r"(dst), "l"(src), "r"(sz), "r"(mbar) : "memory");
}
__device__ __forceinline__ int ld_acq(const int* p) {
    int v; asm volatile("ld.acquire.gpu.global.s32 %0, [%1];" : "=r"(v) : "l"(p) : "memory");
    return v;
}
__device__ __forceinline__ void st_rel(int* p, int v) {
    asm volatile("st.release.gpu.global.s32 [%0], %1;" :: "l"(p), "r"(v) : "memory");
}
__device__ __forceinline__ float ld_cv(const float* p) {
    float v; asm volatile("ld.volatile.global.f32 %0, [%1];" : "=f"(v) : "l"(p) : "memory");
    return v;
}
__device__ __forceinline__ float pf(uint32_t hw, uint32_t lw, uint32_t sel) {
    return __uint_as_float(__byte_perm(hw, lw, sel));
}
__device__ __forceinline__ float warp_reduce16(float v) {
    v += __shfl_xor_sync(0xffffffffu, v, 8);
    v += __shfl_xor_sync(0xffffffffu, v, 4);
    v += __shfl_xor_sync(0xffffffffu, v, 2);
    v += __shfl_xor_sync(0xffffffffu, v, 1);
    return v;
}
#define BAR_ALL()  asm volatile("bar.sync 0, 544;" ::: "memory")
#define BAR_CONS() asm volatile("bar.sync 1, 512;" ::: "memory")

// ---------------- persistent warp-specialized split worker ----------------
__global__ __launch_bounds__(TPB, 1)
void pann_ws(const int* __restrict__ xs,
             const float* __restrict__ lin_w,
             const float* __restrict__ lin_b,
             float* __restrict__ out,
             int S, int nItems)
{
    extern __shared__ unsigned char smem[];
    float* vb = (float*)(smem + SM_V);          // [2 bufs][2 vecs][256]
    int4* s_item = (int4*)(smem + SM_ITEM);

    const int tid  = threadIdx.x;
    const int warp = tid >> 5;
    const int lane = tid & 31;
    const uint32_t fullb  = smem_u32(smem + SM_FULL);
    const uint32_t emptyb = smem_u32(smem + SM_EMPTY);
    const uint32_t wsm    = smem_u32(smem + SM_W);

    if (tid == 0) {
        #pragma unroll
        for (int q = 0; q < NCHUNK; ++q) {
            mbar_init(fullb  + q * 8, 1);
            mbar_init(emptyb + q * 8, 4);   // 4 warps per chunk
        }
    }
    BAR_ALL();

    int pfull = 0;                      // this warp's parity on full[myq]
    int pe[NCHUNK] = {1, 1, 1, 1};      // producer parities on empty[]

    for (;;) {
        if (tid == 0) {
            const int idx = atomicAdd(&g_next, 1);
            *s_item = (idx < nItems) ? g_items[idx] : make_int4(0, 0, -1, 3);
        }
        BAR_ALL();
        const int4 it = *s_item;
        if (it.z < 0) return;
        if (it.z == 0) continue;
        const int b = it.x, start = it.y, count = it.z, dir = it.w;
        const int* xrow = xs + (size_t)b * S;

        if (warp == NCW) {
            // ================= PRODUCER =================
            if (lane == 0) {
                const unsigned char* wbase = (dir == 1) ? g_wb : g_wf;
                for (int t = 0; t < count; ++t) {
                    const int sidx = (dir == 1) ? (start + count - 1 - t) : (start + t);
                    const int a = __ldg(xrow + sidx);
                    const unsigned char* sym = wbase + (size_t)a * SYMB;
                    #pragma unroll
                    for (int q = 0; q < NCHUNK; ++q) {
                        mbar_wait(emptyb + q * 8, pe[q]);
                        pe[q] ^= 1;
                        mbar_expect_tx(fullb + q * 8, CHUNKB);
                        bulk_ld(wsm + q * CHUNKB, sym + q * CHUNKB, CHUNKB,
                                fullb + q * 8);
                    }
                }
            }
            __syncwarp();
        } else {
            // ================= CONSUMERS =================
            const int myq = warp >> 2;
            const int rb  = warp * 16;                    // global row base
            const unsigned char* chb =
                smem + SM_W + myq * CHUNKB + (size_t)((warp & 3) * 16) * ROWB;
            const unsigned char* ph = chb + lane * 16;    // hi slice
            const unsigned char* pl = chb + 512 + lane * 8;

            if (dir == 1) {
                if (tid < NST) { vb[tid] = lin_w[tid]; vb[256 + tid] = lin_w[256 + tid]; }
            } else {
                if (tid < NST) vb[tid] = (tid == 0) ? 1.0f : 0.0f;
            }
            BAR_CONS();

            int cur = 0;
            for (int t = 0; t < count; ++t) {
                float* vsrc = vb + cur * 512;
                float* vdst = vb + (cur ^ 1) * 512;

                const float4 h0 = ((const float4*)vsrc)[2 * lane];
                const float4 h1 = ((const float4*)vsrc)[2 * lane + 1];
                float4 g0, g1;
                if (dir == 1) {
                    g0 = ((const float4*)(vsrc + 256))[2 * lane];
                    g1 = ((const float4*)(vsrc + 256))[2 * lane + 1];
                }

                mbar_wait(fullb + myq * 8, pfull);
                pfull ^= 1;

                if (dir != 1) {
                    #pragma unroll
                    for (int r = 0; r < 16; r += 2) {
                        const uint4 Ha = *(const uint4*)(ph + r * ROWB);
                        const uint2 La = *(const uint2*)(pl + r * ROWB);
                        const uint4 Hb = *(const uint4*)(ph + (r + 1) * ROWB);
                        const uint2 Lb = *(const uint2*)(pl + (r + 1) * ROWB);

                        float sA =
                              pf(Ha.x, La.x, 0x1044u)*h0.x + pf(Ha.x, La.x, 0x3255u)*h0.y
                            + pf(Ha.y, La.x, 0x1066u)*h0.z + pf(Ha.y, La.x, 0x3277u)*h0.w
                            + pf(Ha.z, La.y, 0x1044u)*h1.x + pf(Ha.z, La.y, 0x3255u)*h1.y
                            + pf(Ha.w, La.y, 0x1066u)*h1.z + pf(Ha.w, La.y, 0x3277u)*h1.w;
                        float sB =
                              pf(Hb.x, Lb.x, 0x1044u)*h0.x + pf(Hb.x, Lb.x, 0x3255u)*h0.y
                            + pf(Hb.y, Lb.x, 0x1066u)*h0.z + pf(Hb.y, Lb.x, 0x3277u)*h0.w
                            + pf(Hb.z, Lb.y, 0x1044u)*h1.x + pf(Hb.z, Lb.y, 0x3255u)*h1.y
                            + pf(Hb.w, Lb.y, 0x1066u)*h1.z + pf(Hb.w, Lb.y, 0x3277u)*h1.w;

                        const float oA = __shfl_xor_sync(0xffffffffu, sA, 16);
                        const float oB = __shfl_xor_sync(0xffffffffu, sB, 16);
                        float v = (lane < 16) ? (sA + oA) : (sB + oB);
                        v = warp_reduce16(v);
                        if (lane == 0)  vdst[rb + r]     = v;
                        if (lane == 16) vdst[rb + r + 1] = v;
                    }
                } else {
                    #pragma unroll
                    for (int r = 0; r < 16; ++r) {
                        const uint4 H  = *(const uint4*)(ph + r * ROWB);
                        const uint2 Lw = *(const uint2*)(pl + r * ROWB);
                        const float e0 = pf(H.x, Lw.x, 0x1044u);
                        const float e1 = pf(H.x, Lw.x, 0x3255u);
                        const float e2 = pf(H.y, Lw.x, 0x1066u);
                        const float e3 = pf(H.y, Lw.x, 0x3277u);
                        const float e4 = pf(H.z, Lw.y, 0x1044u);
                        const float e5 = pf(H.z, Lw.y, 0x3255u);
                        const float e6 = pf(H.w, Lw.y, 0x1066u);
                        const float e7 = pf(H.w, Lw.y, 0x3277u);

                        float sA = e0*h0.x + e1*h0.y + e2*h0.z + e3*h0.w
                                 + e4*h1.x + e5*h1.y + e6*h1.z + e7*h1.w;   // k=0
                        float sB = e0*g0.x + e1*g0.y + e2*g0.z + e3*g0.w
                                 + e4*g1.x + e5*g1.y + e6*g1.z + e7*g1.w;   // k=1

                        const float oA = __shfl_xor_sync(0xffffffffu, sA, 16);
                        const float oB = __shfl_xor_sync(0xffffffffu, sB, 16);
                        float v = (lane < 16) ? (sA + oA) : (sB + oB);
                        v = warp_reduce16(v);
                        if (lane == 0)  vdst[rb + r]       = v;
                        if (lane == 16) vdst[256 + rb + r] = v;
                    }
                }
                __syncwarp();
                if (lane == 0) mbar_arrive(emptyb + myq * 8);
                BAR_CONS();
                cur ^= 1;
            }

            float* vfin = vb + cur * 512;
            if (dir == 0) {
                if (tid < 64)
                    ((float4*)g_hmid[b])[tid] = ((const float4*)vfin)[tid];
                BAR_CONS();
                if (tid == 0) { __threadfence(); st_rel(&g_flag[b], 1); }
            } else if (dir == 2) {
                if (warp < 2) {
                    float s = 0.0f;
                    #pragma unroll
                    for (int i = lane; i < NST; i += 32)
                        s += lin_w[warp * NST + i] * vfin[i];
                    s += __shfl_xor_sync(0xffffffffu, s, 16);
                    s = warp_reduce16(s);
                    if (lane == 0) out[b * 2 + warp] = s + lin_b[warp];
                }
            } else {
                if (tid == 0) { while (ld_acq(&g_flag[b]) == 0) { } }
                BAR_CONS();
                if (warp < 2) {
                    float s = 0.0f;
                    #pragma unroll
                    for (int i = lane; i < NST; i += 32)
                        s += vfin[warp * NST + i] * ld_cv(&g_hmid[b][i]);
                    s += __shfl_xor_sync(0xffffffffu, s, 16);
                    s = warp_reduce16(s);
                    if (lane == 0) out[b * 2 + warp] = s + lin_b[warp];
                }
            }
        }
    }
}

// ---------------- fallback (plain R1) for unexpected shapes ----------------
__global__ __launch_bounds__(512, 1)
void pann_chain_fp32(const int* __restrict__ xs,
                     const int* __restrict__ lengths,
                     const float* __restrict__ W,
                     const float* __restrict__ lin_w,
                     const float* __restrict__ lin_b,
                     float* __restrict__ out,
                     int S)
{
    __shared__ float hbuf[2][NST];
    const int b = blockIdx.x, tid = threadIdx.x, warp = tid >> 5, lane = tid & 31;
    if (tid < NST) hbuf[0][tid] = (tid == 0) ? 1.0f : 0.0f;
    const int L = lengths[b];
    const int* xrow = xs + (size_t)b * S;
    __syncthreads();
    int cur = 0;
    const int i0 = warp * 16;
    for (int t = 0; t < L; ++t) {
        const int a = __ldg(xrow + t);
        const float* Wa = W + (size_t)a * (NST * NST);
        const float* hsrc = hbuf[cur];
        float* hdst = hbuf[cur ^ 1];
        const float4 hA = ((const float4*)hsrc)[lane];
        const float4 hB = ((const float4*)hsrc)[32 + lane];
        #pragma unroll 4
        for (int r = 0; r < 16; ++r) {
            const int i = i0 + r;
            const float4* p = (const float4*)(Wa + (size_t)i * NST + lane * 4);
            const float4 wA = p[0];
            const float4 wB = p[32];
            float s = wA.x*hA.x + wA.y*hA.y + wA.z*hA.z + wA.w*hA.w
                    + wB.x*hB.x + wB.y*hB.y + wB.z*hB.z + wB.w*hB.w;
            s += __shfl_xor_sync(0xffffffffu, s, 16);
            s = warp_reduce16(s);
            if (lane == 0) hdst[i] = s;
        }
        __syncthreads();
        cur ^= 1;
    }
    const float* hf = hbuf[cur];
    if (warp < 2) {
        float s = 0.0f;
        #pragma unroll
        for (int i = lane; i < NST; i += 32) s += lin_w[warp * NST + i] * hf[i];
        s += __shfl_xor_sync(0xffffffffu, s, 16);
        s = warp_reduce16(s);
        if (lane == 0) out[b * 2 + warp] = s + lin_b[warp];
    }
}

extern "C" void kernel_launch(void* const* d_in, const int* in_sizes, int n_in,
                              void* d_out, int out_size)
{
    const int*   xs      = (const int*)d_in[0];
    const int*   lengths = (const int*)d_in[1];
    const float* W       = (const float*)d_in[2];
    const float* lin_w   = (const float*)d_in[3];
    const float* lin_b   = (const float*)d_in[4];
    float*       out     = (float*)d_out;

    const int B = in_sizes[1];
    const int S = in_sizes[0] / B;
    const int A = in_sizes[2] / (NST * NST);

    if (A >= 1 && A <= MAXA && B >= 1 && B <= MAXB) {
        static bool attr_set = false;
        if (!attr_set) {
            cudaFuncSetAttribute(pann_ws,
                                 cudaFuncAttributeMaxDynamicSharedMemorySize,
                                 SMEM_TOTAL);
            attr_set = true;
        }
        dim3 qgrid(NST / 32, NST / 32, A);
        pann_qt<<<qgrid, dim3(32, 8)>>>(W);
        pann_sched<<<1, 128>>>(lengths, B);
        pann_ws<<<KCTA, TPB, SMEM_TOTAL>>>(xs, lin_w, lin_b, out, S, 2 * B);
    } else {
        pann_chain_fp32<<<B, 512>>>(xs, lengths, W, lin_w, lin_b, out, S);
    }
}